// round 5
// baseline (speedup 1.0000x reference)
#include <cuda_runtime.h>
#include <cuda_bf16.h>

// Problem constants (fixed by the reference)
#define NODES 100000
#define EDGES 1600000
#define IN_C  128
#define HID_C 128
#define OUT_C 64

// -------- scratch (no allocation allowed -> __device__ globals) --------
__device__ float g_deg[NODES];
__device__ float g_deginv[NODES];
__device__ float g_h1[NODES * HID_C];    // scaled projection, layer 1
__device__ float g_out1[NODES * HID_C];  // aggregated layer-1 output (init to b1)
__device__ float g_h2[NODES * OUT_C];    // scaled projection, layer 2

// vectorized no-return global reduction (REDG pipe, 16B/op)
__device__ __forceinline__ void red_add_v4(float4* p, float4 v) {
    asm volatile("red.global.add.v4.f32 [%0], {%1, %2, %3, %4};"
                 :: "l"(p), "f"(v.x), "f"(v.y), "f"(v.z), "f"(v.w)
                 : "memory");
}

// -------- init: out1 <- b1 broadcast, out <- b2 broadcast, deg <- 0 --------
__global__ void init_kernel(const float* __restrict__ b1,
                            const float* __restrict__ b2,
                            float* __restrict__ outp) {
    int i = blockIdx.x * blockDim.x + threadIdx.x;
    if (i < NODES * HID_C) g_out1[i] = b1[i & (HID_C - 1)];
    if (i < NODES * OUT_C) outp[i]   = b2[i & (OUT_C - 1)];
    if (i < NODES)         g_deg[i]  = 0.0f;
}

// -------- out-degree via scalar RED --------
__global__ void degree_kernel(const int* __restrict__ src) {
    int i = blockIdx.x * blockDim.x + threadIdx.x;
    if (i < EDGES) atomicAdd(&g_deg[src[i]], 1.0f);
}

__global__ void deginv_kernel() {
    int i = blockIdx.x * blockDim.x + threadIdx.x;
    if (i < NODES) g_deginv[i] = 1.0f / fmaxf(g_deg[i], 1.0f);
}

// -------- tiled SGEMM: C[M,NOUT] = op(A[M,128]) @ B[128,NOUT], then *deg_inv --------
// BM=64, BN=64, BK=16, 256 threads, 4x4 per thread.
// SECOND: A = relu(g_out1) (bias folded into init), C = g_h2. else A = x param, C = g_h1.
template <int NOUT, bool SECOND>
__global__ __launch_bounds__(256) void gemm_kernel(const float* __restrict__ Ain,
                                                   const float* __restrict__ B,
                                                   int M) {
    const float* A = SECOND ? g_out1 : Ain;
    float*       C = SECOND ? g_h2   : g_h1;

    __shared__ float As[16][64];  // transposed: As[k][row]
    __shared__ float Bs[16][64];

    const int tid = threadIdx.x;
    const int tx = tid & 15;        // col group (4 cols each)
    const int ty = tid >> 4;        // row group (4 rows each)
    const int rowBase = blockIdx.y * 64;
    const int colBase = blockIdx.x * 64;

    // A-load mapping: one float4 per thread: local row = tid/4, k-quad = tid%4
    const int ar = tid >> 2;
    const int ac = tid & 3;
    // B-load mapping: local k-row = tid/16, col-quad = tid%16
    const int br = tid >> 4;
    const int bc = tid & 15;

    float acc[4][4];
#pragma unroll
    for (int i = 0; i < 4; i++)
#pragma unroll
        for (int j = 0; j < 4; j++) acc[i][j] = 0.0f;

    for (int k0 = 0; k0 < 128; k0 += 16) {
        // load A tile (transposed into smem)
        {
            int grow = rowBase + ar;
            float4 a = make_float4(0.f, 0.f, 0.f, 0.f);
            if (grow < M)
                a = reinterpret_cast<const float4*>(A + (size_t)grow * 128 + k0)[ac];
            if (SECOND) {
                a.x = fmaxf(a.x, 0.f); a.y = fmaxf(a.y, 0.f);
                a.z = fmaxf(a.z, 0.f); a.w = fmaxf(a.w, 0.f);
            }
            As[ac * 4 + 0][ar] = a.x;
            As[ac * 4 + 1][ar] = a.y;
            As[ac * 4 + 2][ar] = a.z;
            As[ac * 4 + 3][ar] = a.w;
        }
        // load B tile
        {
            float4 b = reinterpret_cast<const float4*>(B + (size_t)(k0 + br) * NOUT + colBase)[bc];
            *reinterpret_cast<float4*>(&Bs[br][bc * 4]) = b;
        }
        __syncthreads();

#pragma unroll
        for (int k = 0; k < 16; k++) {
            float4 av = *reinterpret_cast<float4*>(&As[k][ty * 4]);
            float4 bv = *reinterpret_cast<float4*>(&Bs[k][tx * 4]);
            float a[4] = {av.x, av.y, av.z, av.w};
            float b[4] = {bv.x, bv.y, bv.z, bv.w};
#pragma unroll
            for (int i = 0; i < 4; i++)
#pragma unroll
                for (int j = 0; j < 4; j++) acc[i][j] += a[i] * b[j];
        }
        __syncthreads();
    }

#pragma unroll
    for (int i = 0; i < 4; i++) {
        int row = rowBase + ty * 4 + i;
        if (row < M) {
            float s = g_deginv[row];
            float4 o = make_float4(acc[i][0] * s, acc[i][1] * s, acc[i][2] * s, acc[i][3] * s);
            *reinterpret_cast<float4*>(C + (size_t)row * NOUT + colBase + tx * 4) = o;
        }
    }
}

// -------- layer-1 scatter: warp per edge, 32 x float4 = 128 floats --------
__global__ void scatter128_kernel(const int* __restrict__ src,
                                  const int* __restrict__ dst) {
    int gtid = blockIdx.x * blockDim.x + threadIdx.x;
    int e = gtid >> 5;
    int lane = gtid & 31;
    if (e >= EDGES) return;
    int s = src[e];
    int d = dst[e];
    float4 v = reinterpret_cast<const float4*>(g_h1)[s * 32 + lane];
    red_add_v4(reinterpret_cast<float4*>(g_out1) + d * 32 + lane, v);
}

// -------- layer-2 scatter: half-warp per edge, 16 x float4 = 64 floats --------
__global__ void scatter64_kernel(const int* __restrict__ src,
                                 const int* __restrict__ dst,
                                 float* __restrict__ outp) {
    int gtid = blockIdx.x * blockDim.x + threadIdx.x;
    int e = gtid >> 4;
    int lane = gtid & 15;
    if (e >= EDGES) return;
    int s = src[e];
    int d = dst[e];
    float4 v = reinterpret_cast<const float4*>(g_h2)[s * 16 + lane];
    red_add_v4(reinterpret_cast<float4*>(outp) + d * 16 + lane, v);
}

extern "C" void kernel_launch(void* const* d_in, const int* in_sizes, int n_in,
                              void* d_out, int out_size) {
    const float* x  = (const float*)d_in[0];
    const int*   ei = (const int*)d_in[1];   // [2, E]: src then dst
    const float* W1 = (const float*)d_in[2];
    const float* b1 = (const float*)d_in[3];
    const float* W2 = (const float*)d_in[4];
    const float* b2 = (const float*)d_in[5];
    float* outp = (float*)d_out;

    const int* src = ei;
    const int* dst = ei + EDGES;

    // 1) init accumulators (bias broadcast) + zero degrees
    init_kernel<<<(NODES * HID_C + 255) / 256, 256>>>(b1, b2, outp);
    // 2) out-degrees
    degree_kernel<<<(EDGES + 255) / 256, 256>>>(src);
    // 3) reciprocal
    deginv_kernel<<<(NODES + 255) / 256, 256>>>();
    // 4) h1 = (x @ W1) * deg_inv
    {
        dim3 grid(HID_C / 64, (NODES + 63) / 64);
        gemm_kernel<HID_C, false><<<grid, 256>>>(x, W1, NODES);
    }
    // 5) out1 += scatter h1[src] -> dst  (v4 global reductions)
    {
        long long threads = (long long)EDGES * 32;
        scatter128_kernel<<<(unsigned)((threads + 255) / 256), 256>>>(src, dst);
    }
    // 6) h2 = (relu(out1) @ W2) * deg_inv
    {
        dim3 grid(OUT_C / 64, (NODES + 63) / 64);
        gemm_kernel<OUT_C, true><<<grid, 256>>>(nullptr, W2, NODES);
    }
    // 7) out += scatter h2[src] -> dst
    {
        long long threads = (long long)EDGES * 16;
        scatter64_kernel<<<(unsigned)((threads + 255) / 256), 256>>>(src, dst, outp);
    }
}